// round 13
// baseline (speedup 1.0000x reference)
#include <cuda_runtime.h>
#include <cuda_bf16.h>
#include <cstdint>

// Problem constants
#define N_    16384
#define E_    262144
#define IN_   128
#define H_    256
#define OUT_  256
#define L_    4
#define HEADS_ 8
#define OC_   32
#define B_    64
#define NB_   256

// ---------------- scratch (static device globals; no allocations) ----------------
__device__ float g_x[N_ * H_];
__device__ float g_xw[N_ * H_];
__device__ float g_h[N_ * H_];
__device__ float g_out[N_ * H_];
__device__ float g_qkv[N_ * 3 * H_];
__device__ float g_o[N_ * H_];
__device__ float g_ssrc[N_ * HEADS_];
__device__ float g_sdst[N_ * HEADS_];

// CSR of incoming edges
__device__ int g_cnt[N_];
__device__ int g_rowptr[N_ + 1];
__device__ int g_csrc[E_];

// bf16 hi/lo split buffers
__device__ __nv_bfloat16 g_xhi[N_ * H_],     g_xlo[N_ * H_];
__device__ __nv_bfloat16 g_ahi[N_ * H_],     g_alo[N_ * H_];
__device__ __nv_bfloat16 g_ohi[N_ * H_],     g_olo[N_ * H_];
__device__ __nv_bfloat16 g_hhi[N_ * 2 * H_], g_hlo[N_ * 2 * H_];

// weight splits
#define WI_OFF   0
#define WG_OFF   32768
#define INW_OFF  294912
#define OW_OFF   1081344
#define MW1_OFF  1343488
#define MW2_OFF  1867776
#define WO_OFF   2392064
#define WTOT     2457600
__device__ __nv_bfloat16 g_whi[WTOT], g_wlo[WTOT];

// ================= helpers =================
__device__ __forceinline__ void split2(float v, __nv_bfloat16& hi, __nv_bfloat16& lo) {
    hi = __float2bfloat16(v);
    lo = __float2bfloat16(v - __bfloat162float(hi));
}

__device__ __forceinline__ void ldmatrix_x4(uint32_t* r, uint32_t addr) {
    asm volatile("ldmatrix.sync.aligned.m8n8.x4.shared.b16 {%0,%1,%2,%3}, [%4];"
                 : "=r"(r[0]), "=r"(r[1]), "=r"(r[2]), "=r"(r[3]) : "r"(addr));
}

__device__ __forceinline__ void mma_bf16(float* d, const uint32_t* a, const uint32_t* b) {
    asm volatile("mma.sync.aligned.m16n8k16.row.col.f32.bf16.bf16.f32 "
                 "{%0,%1,%2,%3}, {%4,%5,%6,%7}, {%8,%9}, {%0,%1,%2,%3};"
                 : "+f"(d[0]), "+f"(d[1]), "+f"(d[2]), "+f"(d[3])
                 : "r"(a[0]), "r"(a[1]), "r"(a[2]), "r"(a[3]), "r"(b[0]), "r"(b[1]));
}

// ================= tensor-core GEMM: C[M,Nn] = A[M,K] @ B[Nn,K]^T =================
// bf16x3 emulated fp32. 128x128 CTA tile, 8 warps (32x64), K chunks of 32,
// 3-stage cp.async pipeline, 32 KB/stage -> 96 KB smem -> 2 CTAs/SM.
#define GEMM_STAGE 32768
#define GEMM_SMEM  (3 * GEMM_STAGE)

// 64B rows: swizzled 16B-slot = c16 ^ ((row>>1)&3)
__device__ __forceinline__ uint32_t sw_off(int row, int c16) {
    return (uint32_t)(row * 64 + ((c16 ^ ((row >> 1) & 3)) << 4));
}

template <bool RELU>
__global__ __launch_bounds__(256, 2) void mma_gemm_k(
    const __nv_bfloat16* __restrict__ Ahi, const __nv_bfloat16* __restrict__ Alo,
    const __nv_bfloat16* __restrict__ Bhi, const __nv_bfloat16* __restrict__ Blo,
    const float* __restrict__ bias,
    float* __restrict__ C, __nv_bfloat16* __restrict__ Chi, __nv_bfloat16* __restrict__ Clo,
    int M, int Nn, int K)
{
    extern __shared__ char smem[];
    const uint32_t sbase = (uint32_t)__cvta_generic_to_shared(smem);
    const int tid = threadIdx.x, lane = tid & 31, wid = tid >> 5;
    const int wm = wid & 3, wn = wid >> 2;
    const int brow = blockIdx.y, bcol = blockIdx.x;
    const int NC = K >> 5;                         // K chunks of 32

    const __nv_bfloat16* srcs[4] = {
        Ahi + (size_t)(brow * 128) * K, Alo + (size_t)(brow * 128) * K,
        Bhi + (size_t)(bcol * 128) * K, Blo + (size_t)(bcol * 128) * K };

    // stage one K=32 chunk: 4 arrays x 128 rows x 64B
    auto issue = [&](int kc, int buf) {
        uint32_t bb = sbase + buf * GEMM_STAGE;
        int row = tid >> 2, c16 = tid & 3;
        uint32_t d = bb + sw_off(row, c16);
#pragma unroll
        for (int arr = 0; arr < 4; arr++) {
            const void* g0 = srcs[arr] + (size_t)row * K + kc * 32 + c16 * 8;
            const void* g1 = srcs[arr] + (size_t)(row + 64) * K + kc * 32 + c16 * 8;
            asm volatile("cp.async.cg.shared.global [%0], [%1], 16;"
                         :: "r"(d + arr * 8192), "l"(g0));
            asm volatile("cp.async.cg.shared.global [%0], [%1], 16;"
                         :: "r"(d + arr * 8192 + sw_off(64, 0)), "l"(g1));
        }
        asm volatile("cp.async.commit_group;" ::: "memory");
    };

    float acc[2][8][4];
#pragma unroll
    for (int i = 0; i < 2; i++)
#pragma unroll
        for (int j = 0; j < 8; j++)
#pragma unroll
            for (int k = 0; k < 4; k++) acc[i][j][k] = 0.f;

    issue(0, 0);
    if (NC > 1) issue(1, 1);
    if (NC > 2) issue(2, 2);

    const int a_row_off = ((lane >> 3) & 1) * 8 + (lane & 7);
    const int a_c16_off = lane >> 4;
    const int b_row_off = (lane >> 4) * 8 + (lane & 7);
    const int b_c16_off = (lane >> 3) & 1;

    for (int kc = 0; kc < NC; kc++) {
        int pend = NC - 1 - kc;
        if (pend >= 2)      asm volatile("cp.async.wait_group 2;" ::: "memory");
        else if (pend == 1) asm volatile("cp.async.wait_group 1;" ::: "memory");
        else                asm volatile("cp.async.wait_group 0;" ::: "memory");
        __syncthreads();

        const uint32_t bb = sbase + (kc % 3) * GEMM_STAGE;
        const uint32_t aHiB = bb, aLoB = bb + 8192, bHiB = bb + 16384, bLoB = bb + 24576;

#pragma unroll
        for (int ks = 0; ks < 2; ks++) {           // 2 k16 steps per 32-chunk
            uint32_t ahi[2][4], alo[2][4];
#pragma unroll
            for (int mt = 0; mt < 2; mt++) {
                int row = wm * 32 + mt * 16 + a_row_off;
                uint32_t off = sw_off(row, ks * 2 + a_c16_off);
                ldmatrix_x4(ahi[mt], aHiB + off);
                ldmatrix_x4(alo[mt], aLoB + off);
            }
#pragma unroll
            for (int ng = 0; ng < 4; ng++) {
                int row = wn * 64 + ng * 16 + b_row_off;
                uint32_t off = sw_off(row, ks * 2 + b_c16_off);
                uint32_t bhi[4], blo[4];
                ldmatrix_x4(bhi, bHiB + off);
                ldmatrix_x4(blo, bLoB + off);
#pragma unroll
                for (int mt = 0; mt < 2; mt++)
#pragma unroll
                    for (int nt = 0; nt < 2; nt++) {
                        float* c = acc[mt][ng * 2 + nt];
                        mma_bf16(c, ahi[mt], bhi + nt * 2);
                        mma_bf16(c, ahi[mt], blo + nt * 2);
                        mma_bf16(c, alo[mt], bhi + nt * 2);
                    }
            }
        }
        __syncthreads();
        if (kc + 3 < NC) issue(kc + 3, (kc + 3) % 3);
    }

    const int rbase = brow * 128 + wm * 32 + (lane >> 2);
    const int cb0 = bcol * 128 + wn * 64 + (lane & 3) * 2;
#pragma unroll
    for (int mt = 0; mt < 2; mt++)
#pragma unroll
        for (int ni = 0; ni < 8; ni++) {
            float* c = acc[mt][ni];
            int col = cb0 + ni * 8;
            float b0 = bias ? bias[col] : 0.f;
            float b1 = bias ? bias[col + 1] : 0.f;
#pragma unroll
            for (int half = 0; half < 2; half++) {
                int row = rbase + mt * 16 + half * 8;
                float v0 = c[half * 2 + 0] + b0;
                float v1 = c[half * 2 + 1] + b1;
                if (RELU) { v0 = fmaxf(v0, 0.f); v1 = fmaxf(v1, 0.f); }
                size_t o = (size_t)row * Nn + col;
                if (C) *(float2*)(C + o) = make_float2(v0, v1);
                if (Chi) {
                    __nv_bfloat16 h0, l0, h1, l1;
                    split2(v0, h0, l0);
                    split2(v1, h1, l1);
                    *(__nv_bfloat162*)(Chi + o) = __nv_bfloat162(h0, h1);
                    *(__nv_bfloat162*)(Clo + o) = __nv_bfloat162(l0, l1);
                }
            }
        }
}

// ================= conversion kernels =================
__global__ void split_k(const float* __restrict__ x, __nv_bfloat16* __restrict__ hi,
                        __nv_bfloat16* __restrict__ lo, int n)
{
    int i = blockIdx.x * blockDim.x + threadIdx.x;
    if (i >= n) return;
    split2(x[i], hi[i], lo[i]);
}

__global__ void wsplit_t_k(const float* __restrict__ W, __nv_bfloat16* __restrict__ hi,
                           __nv_bfloat16* __restrict__ lo, int K, int Nc, int total)
{
    int i = blockIdx.x * blockDim.x + threadIdx.x;
    if (i >= total) return;
    int KN = K * Nc;
    int l = i / KN, r = i - l * KN;
    int n = r / K, k = r - n * K;
    split2(W[(size_t)l * KN + (size_t)k * Nc + n], hi[i], lo[i]);
}

// ================= CSR build =================
__global__ void csr_zero_k(int* __restrict__ cnt)
{
    int i = blockIdx.x * blockDim.x + threadIdx.x;
    if (i < N_) cnt[i] = 0;
}

__global__ void csr_count_k(const int* __restrict__ ei, int* __restrict__ cnt)
{
    int e = blockIdx.x * blockDim.x + threadIdx.x;
    if (e < E_) atomicAdd(&cnt[ei[E_ + e]], 1);
}

__global__ __launch_bounds__(1024) void csr_scan_k(int* __restrict__ cnt,
                                                   int* __restrict__ rowptr)
{
    __shared__ int ssum[1024];
    int t = threadIdx.x;
    int base = t * 16;
    int loc[16];
    int s = 0;
#pragma unroll
    for (int i = 0; i < 16; i++) { loc[i] = s; s += cnt[base + i]; }
    int own = s;
    ssum[t] = s;
    __syncthreads();
    for (int off = 1; off < 1024; off <<= 1) {
        int v = (t >= off) ? ssum[t - off] : 0;
        __syncthreads();
        ssum[t] += v;
        __syncthreads();
    }
    int excl = ssum[t] - own;
#pragma unroll
    for (int i = 0; i < 16; i++) {
        rowptr[base + i] = excl + loc[i];
        cnt[base + i] = excl + loc[i];
    }
    if (t == 1023) rowptr[N_] = excl + own;
}

__global__ void csr_scatter_k(const int* __restrict__ ei, int* __restrict__ cur,
                              int* __restrict__ csrc)
{
    int e = blockIdx.x * blockDim.x + threadIdx.x;
    if (e >= E_) return;
    int pos = atomicAdd(&cur[ei[E_ + e]], 1);
    csrc[pos] = ei[e];
}

// ================= GAT node scores =================
__global__ void node_scores_k(const float* __restrict__ xw,
                              const float* __restrict__ asrc,
                              const float* __restrict__ adst,
                              float* __restrict__ ssrc, float* __restrict__ sdst)
{
    int n = blockIdx.x, t = threadIdx.x;
    float xv = xw[(size_t)n * H_ + t];
    float a1 = xv * asrc[t];
    float a2 = xv * adst[t];
#pragma unroll
    for (int o = 16; o; o >>= 1) {
        a1 += __shfl_xor_sync(0xffffffffu, a1, o);
        a2 += __shfl_xor_sync(0xffffffffu, a2, o);
    }
    if ((t & 31) == 0) {
        ssrc[n * HEADS_ + (t >> 5)] = a1;
        sdst[n * HEADS_ + (t >> 5)] = a2;
    }
}

// ================= fused GAT aggregate + LN1 (two-phase, chunked) =================
#define GCH 128
__global__ __launch_bounds__(256) void gat_agg_ln_k(
    const int* __restrict__ csrc, const int* __restrict__ rowptr,
    const float* __restrict__ ssrc, const float* __restrict__ sdst,
    const float* __restrict__ xw, const float* __restrict__ x,
    const float* __restrict__ bg, const float* __restrict__ gamma,
    const float* __restrict__ beta, float* __restrict__ out)
{
    __shared__ int   srcsm[GCH];
    __shared__ float esc[GCH * HEADS_];
    int d = blockIdx.x, t = threadIdx.x, hd = t >> 5;
    int beg = rowptr[d], end = rowptr[d + 1];

    float acc = 0.f, asum = 0.f;
    for (int cs = beg; cs < end; cs += GCH) {
        int cn = min(GCH, end - cs);
        if (t < cn) srcsm[t] = csrc[cs + t];
        __syncthreads();
        // phase 1: parallel exp(leaky(score))
        for (int idx = t; idx < cn * HEADS_; idx += 256) {
            int j = idx >> 3, hh = idx & 7;
            float a = ssrc[srcsm[j] * HEADS_ + hh] + sdst[d * HEADS_ + hh];
            a = (a > 0.f) ? a : 0.2f * a;
            esc[idx] = __expf(a);
        }
        __syncthreads();
        // phase 2: weighted accumulate (coalesced xw rows)
        for (int j = 0; j < cn; j++) {
            float e = esc[j * HEADS_ + hd];
            asum += e;
            acc += e * xw[(size_t)srcsm[j] * H_ + t];
        }
        __syncthreads();
    }
    float v = (asum > 0.f) ? acc / asum : 0.f;
    v += bg[t] + x[(size_t)d * H_ + t];

    float s1 = v, s2 = v * v;
#pragma unroll
    for (int o = 16; o; o >>= 1) {
        s1 += __shfl_xor_sync(0xffffffffu, s1, o);
        s2 += __shfl_xor_sync(0xffffffffu, s2, o);
    }
    __shared__ float ws[8], ws2[8];
    if ((t & 31) == 0) { ws[t >> 5] = s1; ws2[t >> 5] = s2; }
    __syncthreads();
    s1 = 0.f; s2 = 0.f;
#pragma unroll
    for (int i = 0; i < 8; i++) { s1 += ws[i]; s2 += ws2[i]; }
    float mean = s1 * (1.f / H_);
    float var = s2 * (1.f / H_) - mean * mean;
    out[(size_t)d * H_ + t] = (v - mean) * rsqrtf(var + 1e-5f) * gamma[t] + beta[t];
}

// ================= LayerNorm =================
__global__ void ln_k(const float* __restrict__ a, const float* __restrict__ b,
                     const float* __restrict__ gamma, const float* __restrict__ beta,
                     const float* __restrict__ addAfter, float* __restrict__ out,
                     __nv_bfloat16* __restrict__ ohi, __nv_bfloat16* __restrict__ olo)
{
    int n = blockIdx.x, t = threadIdx.x;
    size_t idx = (size_t)n * H_ + t;
    float v = a[idx];
    if (b) v += b[idx];
    float s = v, s2 = v * v;
#pragma unroll
    for (int o = 16; o; o >>= 1) {
        s += __shfl_xor_sync(0xffffffffu, s, o);
        s2 += __shfl_xor_sync(0xffffffffu, s2, o);
    }
    __shared__ float ws[8], ws2[8];
    if ((t & 31) == 0) { ws[t >> 5] = s; ws2[t >> 5] = s2; }
    __syncthreads();
    s = 0.f; s2 = 0.f;
#pragma unroll
    for (int i = 0; i < 8; i++) { s += ws[i]; s2 += ws2[i]; }
    float mean = s * (1.f / H_);
    float var = s2 * (1.f / H_) - mean * mean;
    float y = (v - mean) * rsqrtf(var + 1e-5f) * gamma[t] + beta[t];
    float res = (addAfter ? addAfter[idx] : 0.f) + y;
    if (out) out[idx] = res;
    if (ohi) {
        __nv_bfloat16 hi, lo;
        split2(res, hi, lo);
        ohi[idx] = hi;
        olo[idx] = lo;
    }
}

// ================= dense MHA =================
__global__ __launch_bounds__(256) void mha_k(const float* __restrict__ qkv,
                                             __nv_bfloat16* __restrict__ atthi,
                                             __nv_bfloat16* __restrict__ attlo)
{
    extern __shared__ float sm[];
    float* ks = sm;
    float* vs = sm + NB_ * OC_;
    int b = blockIdx.x / HEADS_;
    int h = blockIdx.x % HEADS_;
    int t = threadIdx.x;

    for (int idx = t; idx < NB_ * OC_; idx += 256) {
        int row = idx >> 5, c = idx & 31;
        const float* base = qkv + (size_t)(b * NB_ + row) * (3 * H_) + h * OC_ + c;
        ks[idx] = base[H_];
        vs[idx] = base[2 * H_];
    }
    __syncthreads();

    const float scale = 0.17677669529663687f;
    float q[OC_];
#pragma unroll
    for (int c = 0; c < OC_; c++)
        q[c] = qkv[(size_t)(b * NB_ + t) * (3 * H_) + h * OC_ + c] * scale;

    float lsum = 0.f;
    float o[OC_];
#pragma unroll
    for (int c = 0; c < OC_; c++) o[c] = 0.f;

    for (int j = 0; j < NB_; j++) {
        float s = 0.f;
#pragma unroll
        for (int c = 0; c < OC_; c++) s += q[c] * ks[j * OC_ + c];
        float p = __expf(s);
        lsum += p;
#pragma unroll
        for (int c = 0; c < OC_; c++) o[c] += p * vs[j * OC_ + c];
    }
    float inv = 1.f / lsum;
    size_t obase = (size_t)(b * NB_ + t) * H_ + h * OC_;
#pragma unroll
    for (int c = 0; c < OC_; c++) {
        __nv_bfloat16 hi, lo;
        split2(o[c] * inv, hi, lo);
        atthi[obase + c] = hi;
        attlo[obase + c] = lo;
    }
}

// ================= launcher =================
extern "C" void kernel_launch(void* const* d_in, const int* in_sizes, int n_in,
                              void* d_out, int out_size)
{
    const float* x_in = (const float*)d_in[0];
    const int*   ei   = (const int*)d_in[1];
    const float* wi   = (const float*)d_in[2];
    const float* bi   = (const float*)d_in[3];
    const float* wg   = (const float*)d_in[4];
    const float* asrc = (const float*)d_in[5];
    const float* adst = (const float*)d_in[6];
    const float* bg   = (const float*)d_in[7];
    const float* g1   = (const float*)d_in[8];
    const float* b1   = (const float*)d_in[9];
    const float* inw  = (const float*)d_in[10];
    const float* inb  = (const float*)d_in[11];
    const float* ow   = (const float*)d_in[12];
    const float* ob   = (const float*)d_in[13];
    const float* g2   = (const float*)d_in[14];
    const float* b2   = (const float*)d_in[15];
    const float* mw1  = (const float*)d_in[16];
    const float* mb1  = (const float*)d_in[17];
    const float* mw2  = (const float*)d_in[18];
    const float* mb2  = (const float*)d_in[19];
    const float* g3   = (const float*)d_in[20];
    const float* b3   = (const float*)d_in[21];
    const float* gf   = (const float*)d_in[22];
    const float* bf   = (const float*)d_in[23];
    const float* wo   = (const float*)d_in[24];
    const float* bo   = (const float*)d_in[25];
    float* out = (float*)d_out;

    float *px, *pxw, *ph, *pout, *pqkv, *po, *pss, *psd;
    int *pcnt, *prp, *pcsrc;
    __nv_bfloat16 *pxhi, *pxlo, *pahi, *palo, *pohi, *polo, *phhi, *phlo, *pwhi, *pwlo;
    cudaGetSymbolAddress((void**)&px,   g_x);
    cudaGetSymbolAddress((void**)&pxw,  g_xw);
    cudaGetSymbolAddress((void**)&ph,   g_h);
    cudaGetSymbolAddress((void**)&pout, g_out);
    cudaGetSymbolAddress((void**)&pqkv, g_qkv);
    cudaGetSymbolAddress((void**)&po,   g_o);
    cudaGetSymbolAddress((void**)&pss,  g_ssrc);
    cudaGetSymbolAddress((void**)&psd,  g_sdst);
    cudaGetSymbolAddress((void**)&pcnt, g_cnt);
    cudaGetSymbolAddress((void**)&prp,  g_rowptr);
    cudaGetSymbolAddress((void**)&pcsrc, g_csrc);
    cudaGetSymbolAddress((void**)&pxhi, g_xhi);
    cudaGetSymbolAddress((void**)&pxlo, g_xlo);
    cudaGetSymbolAddress((void**)&pahi, g_ahi);
    cudaGetSymbolAddress((void**)&palo, g_alo);
    cudaGetSymbolAddress((void**)&pohi, g_ohi);
    cudaGetSymbolAddress((void**)&polo, g_olo);
    cudaGetSymbolAddress((void**)&phhi, g_hhi);
    cudaGetSymbolAddress((void**)&phlo, g_hlo);
    cudaGetSymbolAddress((void**)&pwhi, g_whi);
    cudaGetSymbolAddress((void**)&pwlo, g_wlo);

    cudaFuncSetAttribute((const void*)mha_k,
                         cudaFuncAttributeMaxDynamicSharedMemorySize, 64 * 1024);
    cudaFuncSetAttribute((const void*)mma_gemm_k<false>,
                         cudaFuncAttributeMaxDynamicSharedMemorySize, GEMM_SMEM);
    cudaFuncSetAttribute((const void*)mma_gemm_k<true>,
                         cudaFuncAttributeMaxDynamicSharedMemorySize, GEMM_SMEM);

    // ---- CSR build ----
    csr_zero_k<<<N_ / 256, 256>>>(pcnt);
    csr_count_k<<<E_ / 256, 256>>>(ei, pcnt);
    csr_scan_k<<<1, 1024>>>(pcnt, prp);
    csr_scatter_k<<<E_ / 256, 256>>>(ei, pcnt, pcsrc);

    // ---- weight conversions (batched over layers) ----
    wsplit_t_k<<<(32768 + 255) / 256, 256>>>(wi, pwhi + WI_OFF, pwlo + WI_OFF, IN_, H_, 32768);
    wsplit_t_k<<<(4 * 65536 + 255) / 256, 256>>>(wg, pwhi + WG_OFF, pwlo + WG_OFF, H_, H_, 4 * 65536);
    split_k<<<(4 * 196608 + 255) / 256, 256>>>(inw, pwhi + INW_OFF, pwlo + INW_OFF, 4 * 196608);
    split_k<<<(4 * 65536 + 255) / 256, 256>>>(ow, pwhi + OW_OFF, pwlo + OW_OFF, 4 * 65536);
    wsplit_t_k<<<(4 * 131072 + 255) / 256, 256>>>(mw1, pwhi + MW1_OFF, pwlo + MW1_OFF, H_, 2 * H_, 4 * 131072);
    wsplit_t_k<<<(4 * 131072 + 255) / 256, 256>>>(mw2, pwhi + MW2_OFF, pwlo + MW2_OFF, 2 * H_, H_, 4 * 131072);
    wsplit_t_k<<<(65536 + 255) / 256, 256>>>(wo, pwhi + WO_OFF, pwlo + WO_OFF, H_, OUT_, 65536);

    // ---- input projection ----
    split_k<<<(N_ * IN_ + 255) / 256, 256>>>(x_in, phhi, phlo, N_ * IN_);
    mma_gemm_k<true><<<dim3(H_ / 128, N_ / 128), 256, GEMM_SMEM>>>(
        phhi, phlo, pwhi + WI_OFF, pwlo + WI_OFF, bi, px, pxhi, pxlo, N_, H_, IN_);

    for (int l = 0; l < L_; l++) {
        const float* bg_l  = bg  + (size_t)l * H_;
        const float* g1_l  = g1  + (size_t)l * H_;
        const float* b1_l  = b1  + (size_t)l * H_;
        const float* inb_l = inb + (size_t)l * 3 * H_;
        const float* ob_l  = ob  + (size_t)l * H_;
        const float* g2_l  = g2  + (size_t)l * H_;
        const float* b2_l  = b2  + (size_t)l * H_;
        const float* mb1_l = mb1 + (size_t)l * 2 * H_;
        const float* mb2_l = mb2 + (size_t)l * H_;
        const float* g3_l  = g3  + (size_t)l * H_;
        const float* b3_l  = b3  + (size_t)l * H_;

        // ---- GAT local branch ----
        mma_gemm_k<false><<<dim3(H_ / 128, N_ / 128), 256, GEMM_SMEM>>>(
            pxhi, pxlo, pwhi + WG_OFF + l * 65536, pwlo + WG_OFF + l * 65536,
            nullptr, pxw, nullptr, nullptr, N_, H_, H_);
        node_scores_k<<<N_, 256>>>(pxw, asrc + (size_t)l * H_, adst + (size_t)l * H_, pss, psd);
        gat_agg_ln_k<<<N_, 256>>>(pcsrc, prp, pss, psd, pxw, px, bg_l, g1_l, b1_l, ph);

        // ---- global MHA branch ----
        mma_gemm_k<false><<<dim3(3 * H_ / 128, N_ / 128), 256, GEMM_SMEM>>>(
            pxhi, pxlo, pwhi + INW_OFF + l * 196608, pwlo + INW_OFF + l * 196608,
            inb_l, pqkv, nullptr, nullptr, N_, 3 * H_, H_);
        mha_k<<<B_ * HEADS_, 256, 64 * 1024>>>(pqkv, pahi, palo);
        mma_gemm_k<false><<<dim3(H_ / 128, N_ / 128), 256, GEMM_SMEM>>>(
            pahi, palo, pwhi + OW_OFF + l * 65536, pwlo + OW_OFF + l * 65536,
            ob_l, po, nullptr, nullptr, N_, H_, H_);
        ln_k<<<N_, 256>>>(po, px, g2_l, b2_l, ph, pout, pohi, polo);

        // ---- MLP + norm3 ----
        mma_gemm_k<true><<<dim3(2 * H_ / 128, N_ / 128), 256, GEMM_SMEM>>>(
            pohi, polo, pwhi + MW1_OFF + l * 131072, pwlo + MW1_OFF + l * 131072,
            mb1_l, nullptr, phhi, phlo, N_, 2 * H_, H_);
        mma_gemm_k<false><<<dim3(H_ / 128, N_ / 128), 256, GEMM_SMEM>>>(
            phhi, phlo, pwhi + MW2_OFF + l * 131072, pwlo + MW2_OFF + l * 131072,
            mb2_l, ph, nullptr, nullptr, N_, H_, 2 * H_);
        ln_k<<<N_, 256>>>(pout, ph, g3_l, b3_l, nullptr, px, pxhi, pxlo);
    }

    // final LN + output projection
    ln_k<<<N_, 256>>>(px, nullptr, gf, bf, nullptr, nullptr, pahi, palo);
    mma_gemm_k<false><<<dim3(OUT_ / 128, N_ / 128), 256, GEMM_SMEM>>>(
        pahi, palo, pwhi + WO_OFF, pwlo + WO_OFF, bo, out, nullptr, nullptr, N_, OUT_, H_);
}

// round 14
// speedup vs baseline: 1.1700x; 1.1700x over previous
#include <cuda_runtime.h>
#include <cuda_bf16.h>
#include <cstdint>

// Problem constants
#define N_    16384
#define E_    262144
#define IN_   128
#define H_    256
#define OUT_  256
#define L_    4
#define HEADS_ 8
#define OC_   32
#define B_    64
#define NB_   256

// ---------------- scratch (static device globals; no allocations) ----------------
__device__ float g_x[N_ * H_];
__device__ float g_xw[N_ * H_];
__device__ float g_h[N_ * H_];
__device__ float g_out[N_ * H_];
__device__ float g_qkv[N_ * 3 * H_];
__device__ float g_o[N_ * H_];
__device__ float g_ssrc[N_ * HEADS_];
__device__ float g_sdst[N_ * HEADS_];

// CSR of incoming edges
__device__ int g_cnt[N_];
__device__ int g_rowptr[N_ + 1];
__device__ int g_csrc[E_];

// bf16 hi/lo split buffers
__device__ __nv_bfloat16 g_xhi[N_ * H_],     g_xlo[N_ * H_];
__device__ __nv_bfloat16 g_ahi[N_ * H_],     g_alo[N_ * H_];
__device__ __nv_bfloat16 g_ohi[N_ * H_],     g_olo[N_ * H_];
__device__ __nv_bfloat16 g_hhi[N_ * 2 * H_], g_hlo[N_ * 2 * H_];

// weight splits
#define WI_OFF   0
#define WG_OFF   32768
#define INW_OFF  294912
#define OW_OFF   1081344
#define MW1_OFF  1343488
#define MW2_OFF  1867776
#define WO_OFF   2392064
#define WTOT     2457600
__device__ __nv_bfloat16 g_whi[WTOT], g_wlo[WTOT];

// ================= helpers =================
__device__ __forceinline__ void split2(float v, __nv_bfloat16& hi, __nv_bfloat16& lo) {
    hi = __float2bfloat16(v);
    lo = __float2bfloat16(v - __bfloat162float(hi));
}

__device__ __forceinline__ void ldmatrix_x4(uint32_t* r, uint32_t addr) {
    asm volatile("ldmatrix.sync.aligned.m8n8.x4.shared.b16 {%0,%1,%2,%3}, [%4];"
                 : "=r"(r[0]), "=r"(r[1]), "=r"(r[2]), "=r"(r[3]) : "r"(addr));
}

__device__ __forceinline__ void mma_bf16(float* d, const uint32_t* a, const uint32_t* b) {
    asm volatile("mma.sync.aligned.m16n8k16.row.col.f32.bf16.bf16.f32 "
                 "{%0,%1,%2,%3}, {%4,%5,%6,%7}, {%8,%9}, {%0,%1,%2,%3};"
                 : "+f"(d[0]), "+f"(d[1]), "+f"(d[2]), "+f"(d[3])
                 : "r"(a[0]), "r"(a[1]), "r"(a[2]), "r"(a[3]), "r"(b[0]), "r"(b[1]));
}

// packed fp32x2 (Blackwell 2x fp32 path)
__device__ __forceinline__ uint64_t ffma2(uint64_t a, uint64_t b, uint64_t c) {
    uint64_t d;
    asm("fma.rn.f32x2 %0, %1, %2, %3;" : "=l"(d) : "l"(a), "l"(b), "l"(c));
    return d;
}
__device__ __forceinline__ uint64_t pk2(float lo, float hi) {
    uint64_t r;
    asm("mov.b64 %0, {%1, %2};" : "=l"(r) : "f"(lo), "f"(hi));
    return r;
}
__device__ __forceinline__ float2 upk2(uint64_t v) {
    float2 f;
    asm("mov.b64 {%0, %1}, %2;" : "=f"(f.x), "=f"(f.y) : "l"(v));
    return f;
}

// ================= tensor-core GEMM: C[M,Nn] = A[M,K] @ B[Nn,K]^T =================
#define GEMM_STAGE 32768
#define GEMM_SMEM  (3 * GEMM_STAGE)

__device__ __forceinline__ uint32_t sw_off(int row, int c16) {
    return (uint32_t)(row * 64 + ((c16 ^ ((row >> 1) & 3)) << 4));
}

template <bool RELU>
__global__ __launch_bounds__(256, 2) void mma_gemm_k(
    const __nv_bfloat16* __restrict__ Ahi, const __nv_bfloat16* __restrict__ Alo,
    const __nv_bfloat16* __restrict__ Bhi, const __nv_bfloat16* __restrict__ Blo,
    const float* __restrict__ bias,
    float* __restrict__ C, __nv_bfloat16* __restrict__ Chi, __nv_bfloat16* __restrict__ Clo,
    int M, int Nn, int K)
{
    extern __shared__ char smem[];
    const uint32_t sbase = (uint32_t)__cvta_generic_to_shared(smem);
    const int tid = threadIdx.x, lane = tid & 31, wid = tid >> 5;
    const int wm = wid & 3, wn = wid >> 2;
    const int brow = blockIdx.y, bcol = blockIdx.x;
    const int NC = K >> 5;

    const __nv_bfloat16* srcs[4] = {
        Ahi + (size_t)(brow * 128) * K, Alo + (size_t)(brow * 128) * K,
        Bhi + (size_t)(bcol * 128) * K, Blo + (size_t)(bcol * 128) * K };

    auto issue = [&](int kc, int buf) {
        uint32_t bb = sbase + buf * GEMM_STAGE;
        int row = tid >> 2, c16 = tid & 3;
        uint32_t d = bb + sw_off(row, c16);
#pragma unroll
        for (int arr = 0; arr < 4; arr++) {
            const void* g0 = srcs[arr] + (size_t)row * K + kc * 32 + c16 * 8;
            const void* g1 = srcs[arr] + (size_t)(row + 64) * K + kc * 32 + c16 * 8;
            asm volatile("cp.async.cg.shared.global [%0], [%1], 16;"
                         :: "r"(d + arr * 8192), "l"(g0));
            asm volatile("cp.async.cg.shared.global [%0], [%1], 16;"
                         :: "r"(d + arr * 8192 + sw_off(64, 0)), "l"(g1));
        }
        asm volatile("cp.async.commit_group;" ::: "memory");
    };

    float acc[2][8][4];
#pragma unroll
    for (int i = 0; i < 2; i++)
#pragma unroll
        for (int j = 0; j < 8; j++)
#pragma unroll
            for (int k = 0; k < 4; k++) acc[i][j][k] = 0.f;

    issue(0, 0);
    if (NC > 1) issue(1, 1);
    if (NC > 2) issue(2, 2);

    const int a_row_off = ((lane >> 3) & 1) * 8 + (lane & 7);
    const int a_c16_off = lane >> 4;
    const int b_row_off = (lane >> 4) * 8 + (lane & 7);
    const int b_c16_off = (lane >> 3) & 1;

    for (int kc = 0; kc < NC; kc++) {
        int pend = NC - 1 - kc;
        if (pend >= 2)      asm volatile("cp.async.wait_group 2;" ::: "memory");
        else if (pend == 1) asm volatile("cp.async.wait_group 1;" ::: "memory");
        else                asm volatile("cp.async.wait_group 0;" ::: "memory");
        __syncthreads();

        const uint32_t bb = sbase + (kc % 3) * GEMM_STAGE;
        const uint32_t aHiB = bb, aLoB = bb + 8192, bHiB = bb + 16384, bLoB = bb + 24576;

#pragma unroll
        for (int ks = 0; ks < 2; ks++) {
            uint32_t ahi[2][4], alo[2][4];
#pragma unroll
            for (int mt = 0; mt < 2; mt++) {
                int row = wm * 32 + mt * 16 + a_row_off;
                uint32_t off = sw_off(row, ks * 2 + a_c16_off);
                ldmatrix_x4(ahi[mt], aHiB + off);
                ldmatrix_x4(alo[mt], aLoB + off);
            }
#pragma unroll
            for (int ng = 0; ng < 4; ng++) {
                int row = wn * 64 + ng * 16 + b_row_off;
                uint32_t off = sw_off(row, ks * 2 + b_c16_off);
                uint32_t bhi[4], blo[4];
                ldmatrix_x4(bhi, bHiB + off);
                ldmatrix_x4(blo, bLoB + off);
#pragma unroll
                for (int mt = 0; mt < 2; mt++)
#pragma unroll
                    for (int nt = 0; nt < 2; nt++) {
                        float* c = acc[mt][ng * 2 + nt];
                        mma_bf16(c, ahi[mt], bhi + nt * 2);
                        mma_bf16(c, ahi[mt], blo + nt * 2);
                        mma_bf16(c, alo[mt], bhi + nt * 2);
                    }
            }
        }
        __syncthreads();
        if (kc + 3 < NC) issue(kc + 3, (kc + 3) % 3);
    }

    const int rbase = brow * 128 + wm * 32 + (lane >> 2);
    const int cb0 = bcol * 128 + wn * 64 + (lane & 3) * 2;
#pragma unroll
    for (int mt = 0; mt < 2; mt++)
#pragma unroll
        for (int ni = 0; ni < 8; ni++) {
            float* c = acc[mt][ni];
            int col = cb0 + ni * 8;
            float b0 = bias ? bias[col] : 0.f;
            float b1 = bias ? bias[col + 1] : 0.f;
#pragma unroll
            for (int half = 0; half < 2; half++) {
                int row = rbase + mt * 16 + half * 8;
                float v0 = c[half * 2 + 0] + b0;
                float v1 = c[half * 2 + 1] + b1;
                if (RELU) { v0 = fmaxf(v0, 0.f); v1 = fmaxf(v1, 0.f); }
                size_t o = (size_t)row * Nn + col;
                if (C) *(float2*)(C + o) = make_float2(v0, v1);
                if (Chi) {
                    __nv_bfloat16 h0, l0, h1, l1;
                    split2(v0, h0, l0);
                    split2(v1, h1, l1);
                    *(__nv_bfloat162*)(Chi + o) = __nv_bfloat162(h0, h1);
                    *(__nv_bfloat162*)(Clo + o) = __nv_bfloat162(l0, l1);
                }
            }
        }
}

// ================= conversion kernels =================
__global__ void split_k(const float* __restrict__ x, __nv_bfloat16* __restrict__ hi,
                        __nv_bfloat16* __restrict__ lo, int n)
{
    int i = blockIdx.x * blockDim.x + threadIdx.x;
    if (i >= n) return;
    split2(x[i], hi[i], lo[i]);
}

__global__ void wsplit_t_k(const float* __restrict__ W, __nv_bfloat16* __restrict__ hi,
                           __nv_bfloat16* __restrict__ lo, int K, int Nc, int total)
{
    int i = blockIdx.x * blockDim.x + threadIdx.x;
    if (i >= total) return;
    int KN = K * Nc;
    int l = i / KN, r = i - l * KN;
    int n = r / K, k = r - n * K;
    split2(W[(size_t)l * KN + (size_t)k * Nc + n], hi[i], lo[i]);
}

// ================= CSR build =================
__global__ void csr_zero_k(int* __restrict__ cnt)
{
    int i = blockIdx.x * blockDim.x + threadIdx.x;
    if (i < N_) cnt[i] = 0;
}

__global__ void csr_count_k(const int* __restrict__ ei, int* __restrict__ cnt)
{
    int e = blockIdx.x * blockDim.x + threadIdx.x;
    if (e < E_) atomicAdd(&cnt[ei[E_ + e]], 1);
}

__global__ __launch_bounds__(1024) void csr_scan_k(int* __restrict__ cnt,
                                                   int* __restrict__ rowptr)
{
    __shared__ int ssum[1024];
    int t = threadIdx.x;
    int base = t * 16;
    int loc[16];
    int s = 0;
#pragma unroll
    for (int i = 0; i < 16; i++) { loc[i] = s; s += cnt[base + i]; }
    int own = s;
    ssum[t] = s;
    __syncthreads();
    for (int off = 1; off < 1024; off <<= 1) {
        int v = (t >= off) ? ssum[t - off] : 0;
        __syncthreads();
        ssum[t] += v;
        __syncthreads();
    }
    int excl = ssum[t] - own;
#pragma unroll
    for (int i = 0; i < 16; i++) {
        rowptr[base + i] = excl + loc[i];
        cnt[base + i] = excl + loc[i];
    }
    if (t == 1023) rowptr[N_] = excl + own;
}

__global__ void csr_scatter_k(const int* __restrict__ ei, int* __restrict__ cur,
                              int* __restrict__ csrc)
{
    int e = blockIdx.x * blockDim.x + threadIdx.x;
    if (e >= E_) return;
    int pos = atomicAdd(&cur[ei[E_ + e]], 1);
    csrc[pos] = ei[e];
}

// ================= GAT node scores =================
__global__ void node_scores_k(const float* __restrict__ xw,
                              const float* __restrict__ asrc,
                              const float* __restrict__ adst,
                              float* __restrict__ ssrc, float* __restrict__ sdst)
{
    int n = blockIdx.x, t = threadIdx.x;
    float xv = xw[(size_t)n * H_ + t];
    float a1 = xv * asrc[t];
    float a2 = xv * adst[t];
#pragma unroll
    for (int o = 16; o; o >>= 1) {
        a1 += __shfl_xor_sync(0xffffffffu, a1, o);
        a2 += __shfl_xor_sync(0xffffffffu, a2, o);
    }
    if ((t & 31) == 0) {
        ssrc[n * HEADS_ + (t >> 5)] = a1;
        sdst[n * HEADS_ + (t >> 5)] = a2;
    }
}

// ================= fused GAT aggregate + LN1 =================
#define GCH 128
__global__ __launch_bounds__(256) void gat_agg_ln_k(
    const int* __restrict__ csrc, const int* __restrict__ rowptr,
    const float* __restrict__ ssrc, const float* __restrict__ sdst,
    const float* __restrict__ xw, const float* __restrict__ x,
    const float* __restrict__ bg, const float* __restrict__ gamma,
    const float* __restrict__ beta, float* __restrict__ out)
{
    __shared__ int   srcsm[GCH];
    __shared__ float esc[GCH * HEADS_];
    int d = blockIdx.x, t = threadIdx.x, hd = t >> 5;
    int beg = rowptr[d], end = rowptr[d + 1];

    float acc = 0.f, asum = 0.f;
    for (int cs = beg; cs < end; cs += GCH) {
        int cn = min(GCH, end - cs);
        if (t < cn) srcsm[t] = csrc[cs + t];
        __syncthreads();
        for (int idx = t; idx < cn * HEADS_; idx += 256) {
            int j = idx >> 3, hh = idx & 7;
            float a = ssrc[srcsm[j] * HEADS_ + hh] + sdst[d * HEADS_ + hh];
            a = (a > 0.f) ? a : 0.2f * a;
            esc[idx] = __expf(a);
        }
        __syncthreads();
        for (int j = 0; j < cn; j++) {
            float e = esc[j * HEADS_ + hd];
            asum += e;
            acc += e * xw[(size_t)srcsm[j] * H_ + t];
        }
        __syncthreads();
    }
    float v = (asum > 0.f) ? acc / asum : 0.f;
    v += bg[t] + x[(size_t)d * H_ + t];

    float s1 = v, s2 = v * v;
#pragma unroll
    for (int o = 16; o; o >>= 1) {
        s1 += __shfl_xor_sync(0xffffffffu, s1, o);
        s2 += __shfl_xor_sync(0xffffffffu, s2, o);
    }
    __shared__ float ws[8], ws2[8];
    if ((t & 31) == 0) { ws[t >> 5] = s1; ws2[t >> 5] = s2; }
    __syncthreads();
    s1 = 0.f; s2 = 0.f;
#pragma unroll
    for (int i = 0; i < 8; i++) { s1 += ws[i]; s2 += ws2[i]; }
    float mean = s1 * (1.f / H_);
    float var = s2 * (1.f / H_) - mean * mean;
    out[(size_t)d * H_ + t] = (v - mean) * rsqrtf(var + 1e-5f) * gamma[t] + beta[t];
}

// ================= LayerNorm =================
__global__ void ln_k(const float* __restrict__ a, const float* __restrict__ b,
                     const float* __restrict__ gamma, const float* __restrict__ beta,
                     const float* __restrict__ addAfter, float* __restrict__ out,
                     __nv_bfloat16* __restrict__ ohi, __nv_bfloat16* __restrict__ olo)
{
    int n = blockIdx.x, t = threadIdx.x;
    size_t idx = (size_t)n * H_ + t;
    float v = a[idx];
    if (b) v += b[idx];
    float s = v, s2 = v * v;
#pragma unroll
    for (int o = 16; o; o >>= 1) {
        s += __shfl_xor_sync(0xffffffffu, s, o);
        s2 += __shfl_xor_sync(0xffffffffu, s2, o);
    }
    __shared__ float ws[8], ws2[8];
    if ((t & 31) == 0) { ws[t >> 5] = s; ws2[t >> 5] = s2; }
    __syncthreads();
    s = 0.f; s2 = 0.f;
#pragma unroll
    for (int i = 0; i < 8; i++) { s += ws[i]; s2 += ws2[i]; }
    float mean = s * (1.f / H_);
    float var = s2 * (1.f / H_) - mean * mean;
    float y = (v - mean) * rsqrtf(var + 1e-5f) * gamma[t] + beta[t];
    float res = (addAfter ? addAfter[idx] : 0.f) + y;
    if (out) out[idx] = res;
    if (ohi) {
        __nv_bfloat16 hi, lo;
        split2(res, hi, lo);
        ohi[idx] = hi;
        olo[idx] = lo;
    }
}

// ================= dense MHA (packed fp32x2 math) =================
__global__ __launch_bounds__(256) void mha_k(const float* __restrict__ qkv,
                                             __nv_bfloat16* __restrict__ atthi,
                                             __nv_bfloat16* __restrict__ attlo)
{
    extern __shared__ float sm[];          // ks[256*32] ++ vs[256*32] = 64 KB
    float* ks = sm;
    float* vs = sm + NB_ * OC_;
    int b = blockIdx.x / HEADS_;
    int h = blockIdx.x % HEADS_;
    int t = threadIdx.x;                   // query row

    // stage K,V (8-byte vectorized; offsets all even floats -> aligned)
    for (int idx = t; idx < NB_ * OC_ / 2; idx += 256) {
        int row = idx >> 4, c2 = idx & 15;
        const float* base = qkv + (size_t)(b * NB_ + row) * (3 * H_) + h * OC_ + c2 * 2;
        *(uint64_t*)(ks + idx * 2) = *(const uint64_t*)(base + H_);
        *(uint64_t*)(vs + idx * 2) = *(const uint64_t*)(base + 2 * H_);
    }
    __syncthreads();

    const float scale = 0.17677669529663687f;  // 1/sqrt(32)
    const float* qrow = qkv + (size_t)(b * NB_ + t) * (3 * H_) + h * OC_;
    uint64_t q2[16];
#pragma unroll
    for (int i = 0; i < 16; i++)
        q2[i] = pk2(qrow[2 * i] * scale, qrow[2 * i + 1] * scale);

    uint64_t o2[16];
#pragma unroll
    for (int i = 0; i < 16; i++) o2[i] = 0ull;
    float lsum = 0.f;

    const uint64_t* ks2 = (const uint64_t*)ks;
    const uint64_t* vs2 = (const uint64_t*)vs;

    for (int j = 0; j < NB_; j++) {
        uint64_t da = 0ull, db = 0ull;     // two dot chains for ILP
#pragma unroll
        for (int i = 0; i < 16; i += 2) {
            da = ffma2(q2[i],     ks2[j * 16 + i],     da);
            db = ffma2(q2[i + 1], ks2[j * 16 + i + 1], db);
        }
        float2 fa = upk2(da), fb = upk2(db);
        float s = (fa.x + fa.y) + (fb.x + fb.y);
        float p = __expf(s);
        lsum += p;
        uint64_t pp = pk2(p, p);
#pragma unroll
        for (int i = 0; i < 16; i++)
            o2[i] = ffma2(pp, vs2[j * 16 + i], o2[i]);
    }

    float inv = 1.f / lsum;
    size_t obase = (size_t)(b * NB_ + t) * H_ + h * OC_;
#pragma unroll
    for (int i = 0; i < 16; i++) {
        float2 ov = upk2(o2[i]);
        __nv_bfloat16 h0, l0, h1, l1;
        split2(ov.x * inv, h0, l0);
        split2(ov.y * inv, h1, l1);
        *(__nv_bfloat162*)(atthi + obase + 2 * i) = __nv_bfloat162(h0, h1);
        *(__nv_bfloat162*)(attlo + obase + 2 * i) = __nv_bfloat162(l0, l1);
    }
}

// ================= launcher =================
extern "C" void kernel_launch(void* const* d_in, const int* in_sizes, int n_in,
                              void* d_out, int out_size)
{
    const float* x_in = (const float*)d_in[0];
    const int*   ei   = (const int*)d_in[1];
    const float* wi   = (const float*)d_in[2];
    const float* bi   = (const float*)d_in[3];
    const float* wg   = (const float*)d_in[4];
    const float* asrc = (const float*)d_in[5];
    const float* adst = (const float*)d_in[6];
    const float* bg   = (const float*)d_in[7];
    const float* g1   = (const float*)d_in[8];
    const float* b1   = (const float*)d_in[9];
    const float* inw  = (const float*)d_in[10];
    const float* inb  = (const float*)d_in[11];
    const float* ow   = (const float*)d_in[12];
    const float* ob   = (const float*)d_in[13];
    const float* g2   = (const float*)d_in[14];
    const float* b2   = (const float*)d_in[15];
    const float* mw1  = (const float*)d_in[16];
    const float* mb1  = (const float*)d_in[17];
    const float* mw2  = (const float*)d_in[18];
    const float* mb2  = (const float*)d_in[19];
    const float* g3   = (const float*)d_in[20];
    const float* b3   = (const float*)d_in[21];
    const float* gf   = (const float*)d_in[22];
    const float* bf   = (const float*)d_in[23];
    const float* wo   = (const float*)d_in[24];
    const float* bo   = (const float*)d_in[25];
    float* out = (float*)d_out;

    float *px, *pxw, *ph, *pout, *pqkv, *po, *pss, *psd;
    int *pcnt, *prp, *pcsrc;
    __nv_bfloat16 *pxhi, *pxlo, *pahi, *palo, *pohi, *polo, *phhi, *phlo, *pwhi, *pwlo;
    cudaGetSymbolAddress((void**)&px,   g_x);
    cudaGetSymbolAddress((void**)&pxw,  g_xw);
    cudaGetSymbolAddress((void**)&ph,   g_h);
    cudaGetSymbolAddress((void**)&pout, g_out);
    cudaGetSymbolAddress((void**)&pqkv, g_qkv);
    cudaGetSymbolAddress((void**)&po,   g_o);
    cudaGetSymbolAddress((void**)&pss,  g_ssrc);
    cudaGetSymbolAddress((void**)&psd,  g_sdst);
    cudaGetSymbolAddress((void**)&pcnt, g_cnt);
    cudaGetSymbolAddress((void**)&prp,  g_rowptr);
    cudaGetSymbolAddress((void**)&pcsrc, g_csrc);
    cudaGetSymbolAddress((void**)&pxhi, g_xhi);
    cudaGetSymbolAddress((void**)&pxlo, g_xlo);
    cudaGetSymbolAddress((void**)&pahi, g_ahi);
    cudaGetSymbolAddress((void**)&palo, g_alo);
    cudaGetSymbolAddress((void**)&pohi, g_ohi);
    cudaGetSymbolAddress((void**)&polo, g_olo);
    cudaGetSymbolAddress((void**)&phhi, g_hhi);
    cudaGetSymbolAddress((void**)&phlo, g_hlo);
    cudaGetSymbolAddress((void**)&pwhi, g_whi);
    cudaGetSymbolAddress((void**)&pwlo, g_wlo);

    cudaFuncSetAttribute((const void*)mha_k,
                         cudaFuncAttributeMaxDynamicSharedMemorySize, 64 * 1024);
    cudaFuncSetAttribute((const void*)mma_gemm_k<false>,
                         cudaFuncAttributeMaxDynamicSharedMemorySize, GEMM_SMEM);
    cudaFuncSetAttribute((const void*)mma_gemm_k<true>,
                         cudaFuncAttributeMaxDynamicSharedMemorySize, GEMM_SMEM);

    // ---- prologue ordered so early launches (#4/#6) are real GEMMs for ncu ----
    wsplit_t_k<<<(32768 + 255) / 256, 256>>>(wi, pwhi + WI_OFF, pwlo + WI_OFF, IN_, H_, 32768);          // 1
    wsplit_t_k<<<(4 * 65536 + 255) / 256, 256>>>(wg, pwhi + WG_OFF, pwlo + WG_OFF, H_, H_, 4 * 65536);   // 2
    split_k<<<(N_ * IN_ + 255) / 256, 256>>>(x_in, phhi, phlo, N_ * IN_);                                 // 3
    mma_gemm_k<true><<<dim3(H_ / 128, N_ / 128), 256, GEMM_SMEM>>>(                                       // 4
        phhi, phlo, pwhi + WI_OFF, pwlo + WI_OFF, bi, px, pxhi, pxlo, N_, H_, IN_);
    csr_zero_k<<<N_ / 256, 256>>>(pcnt);                                                                  // 5
    mma_gemm_k<false><<<dim3(H_ / 128, N_ / 128), 256, GEMM_SMEM>>>(                                      // 6 <- ncu target
        pxhi, pxlo, pwhi + WG_OFF, pwlo + WG_OFF, nullptr, pxw, nullptr, nullptr, N_, H_, H_);
    csr_count_k<<<E_ / 256, 256>>>(ei, pcnt);
    csr_scan_k<<<1, 1024>>>(pcnt, prp);
    split_k<<<(4 * 196608 + 255) / 256, 256>>>(inw, pwhi + INW_OFF, pwlo + INW_OFF, 4 * 196608);
    split_k<<<(4 * 65536 + 255) / 256, 256>>>(ow, pwhi + OW_OFF, pwlo + OW_OFF, 4 * 65536);
    wsplit_t_k<<<(4 * 131072 + 255) / 256, 256>>>(mw1, pwhi + MW1_OFF, pwlo + MW1_OFF, H_, 2 * H_, 4 * 131072);
    wsplit_t_k<<<(4 * 131072 + 255) / 256, 256>>>(mw2, pwhi + MW2_OFF, pwlo + MW2_OFF, 2 * H_, H_, 4 * 131072);
    wsplit_t_k<<<(65536 + 255) / 256, 256>>>(wo, pwhi + WO_OFF, pwlo + WO_OFF, H_, OUT_, 65536);
    csr_scatter_k<<<E_ / 256, 256>>>(ei, pcnt, pcsrc);

    for (int l = 0; l < L_; l++) {
        const float* bg_l  = bg  + (size_t)l * H_;
        const float* g1_l  = g1  + (size_t)l * H_;
        const float* b1_l  = b1  + (size_t)l * H_;
        const float* inb_l = inb + (size_t)l * 3 * H_;
        const float* ob_l  = ob  + (size_t)l * H_;
        const float* g2_l  = g2  + (size_t)l * H_;
        const float* b2_l  = b2  + (size_t)l * H_;
        const float* mb1_l = mb1 + (size_t)l * 2 * H_;
        const float* mb2_l = mb2 + (size_t)l * H_;
        const float* g3_l  = g3  + (size_t)l * H_;
        const float* b3_l  = b3  + (size_t)l * H_;

        // ---- GAT local branch (layer 0's wg GEMM already done in prologue) ----
        if (l > 0)
            mma_gemm_k<false><<<dim3(H_ / 128, N_ / 128), 256, GEMM_SMEM>>>(
                pxhi, pxlo, pwhi + WG_OFF + l * 65536, pwlo + WG_OFF + l * 65536,
                nullptr, pxw, nullptr, nullptr, N_, H_, H_);
        node_scores_k<<<N_, 256>>>(pxw, asrc + (size_t)l * H_, adst + (size_t)l * H_, pss, psd);
        gat_agg_ln_k<<<N_, 256>>>(pcsrc, prp, pss, psd, pxw, px, bg_l, g1_l, b1_l, ph);

        // ---- global MHA branch ----
        mma_gemm_k<false><<<dim3(3 * H_ / 128, N_ / 128), 256, GEMM_SMEM>>>(
            pxhi, pxlo, pwhi + INW_OFF + l * 196608, pwlo + INW_OFF + l * 196608,
            inb_l, pqkv, nullptr, nullptr, N_, 3 * H_, H_);
        mha_k<<<B_ * HEADS_, 256, 64 * 1024>>>(pqkv, pahi, palo);
        mma_gemm_k<false><<<dim3(H_ / 128, N_ / 128), 256, GEMM_SMEM>>>(
            pahi, palo, pwhi + OW_OFF + l * 65536, pwlo + OW_OFF + l * 65536,
            ob_l, po, nullptr, nullptr, N_, H_, H_);
        ln_k<<<N_, 256>>>(po, px, g2_l, b2_l, ph, pout, pohi, polo);

        // ---- MLP + norm3 ----
        mma_gemm_k<true><<<dim3(2 * H_ / 128, N_ / 128), 256, GEMM_SMEM>>>(
            pohi, polo, pwhi + MW1_OFF + l * 131072, pwlo + MW1_OFF + l * 131072,
            mb1_l, nullptr, phhi, phlo, N_, 2 * H_, H_);
        mma_gemm_k<false><<<dim3(H_ / 128, N_ / 128), 256, GEMM_SMEM>>>(
            phhi, phlo, pwhi + MW2_OFF + l * 131072, pwlo + MW2_OFF + l * 131072,
            mb2_l, ph, nullptr, nullptr, N_, H_, 2 * H_);
        ln_k<<<N_, 256>>>(pout, ph, g3_l, b3_l, nullptr, px, pxhi, pxlo);
    }

    // final LN + output projection
    ln_k<<<N_, 256>>>(px, nullptr, gf, bf, nullptr, nullptr, pahi, palo);
    mma_gemm_k<false><<<dim3(OUT_ / 128, N_ / 128), 256, GEMM_SMEM>>>(
        pahi, palo, pwhi + WO_OFF, pwlo + WO_OFF, bo, out, nullptr, nullptr, N_, OUT_, H_);
}

// round 15
// speedup vs baseline: 1.1714x; 1.0012x over previous
#include <cuda_runtime.h>
#include <cuda_bf16.h>
#include <cstdint>

// Problem constants
#define N_    16384
#define E_    262144
#define IN_   128
#define H_    256
#define OUT_  256
#define L_    4
#define HEADS_ 8
#define OC_   32
#define B_    64
#define NB_   256

// ---------------- scratch (static device globals; no allocations) ----------------
__device__ float g_x[N_ * H_];
__device__ float g_xw[N_ * H_];
__device__ float g_h[N_ * H_];
__device__ float g_out[N_ * H_];
__device__ float g_qkv[N_ * 3 * H_];
__device__ float g_o[N_ * H_];
__device__ float g_ssrc[N_ * HEADS_];
__device__ float g_sdst[N_ * HEADS_];

// CSR of incoming edges
__device__ int g_cnt[N_];
__device__ int g_rowptr[N_ + 1];
__device__ int g_csrc[E_];

// bf16 hi/lo split buffers
__device__ __nv_bfloat16 g_xhi[N_ * H_],     g_xlo[N_ * H_];
__device__ __nv_bfloat16 g_ahi[N_ * H_],     g_alo[N_ * H_];
__device__ __nv_bfloat16 g_ohi[N_ * H_],     g_olo[N_ * H_];
__device__ __nv_bfloat16 g_hhi[N_ * 2 * H_], g_hlo[N_ * 2 * H_];

// weight splits
#define WI_OFF   0
#define WG_OFF   32768
#define INW_OFF  294912
#define OW_OFF   1081344
#define MW1_OFF  1343488
#define MW2_OFF  1867776
#define WO_OFF   2392064
#define WTOT     2457600
__device__ __nv_bfloat16 g_whi[WTOT], g_wlo[WTOT];

// ================= helpers =================
__device__ __forceinline__ void split2(float v, __nv_bfloat16& hi, __nv_bfloat16& lo) {
    hi = __float2bfloat16(v);
    lo = __float2bfloat16(v - __bfloat162float(hi));
}

__device__ __forceinline__ void ldmatrix_x4(uint32_t* r, uint32_t addr) {
    asm volatile("ldmatrix.sync.aligned.m8n8.x4.shared.b16 {%0,%1,%2,%3}, [%4];"
                 : "=r"(r[0]), "=r"(r[1]), "=r"(r[2]), "=r"(r[3]) : "r"(addr));
}

__device__ __forceinline__ void mma_bf16(float* d, const uint32_t* a, const uint32_t* b) {
    asm volatile("mma.sync.aligned.m16n8k16.row.col.f32.bf16.bf16.f32 "
                 "{%0,%1,%2,%3}, {%4,%5,%6,%7}, {%8,%9}, {%0,%1,%2,%3};"
                 : "+f"(d[0]), "+f"(d[1]), "+f"(d[2]), "+f"(d[3])
                 : "r"(a[0]), "r"(a[1]), "r"(a[2]), "r"(a[3]), "r"(b[0]), "r"(b[1]));
}

// packed fp32x2 (Blackwell 2x fp32 path)
__device__ __forceinline__ uint64_t ffma2(uint64_t a, uint64_t b, uint64_t c) {
    uint64_t d;
    asm("fma.rn.f32x2 %0, %1, %2, %3;" : "=l"(d) : "l"(a), "l"(b), "l"(c));
    return d;
}
__device__ __forceinline__ uint64_t pk2(float lo, float hi) {
    uint64_t r;
    asm("mov.b64 %0, {%1, %2};" : "=l"(r) : "f"(lo), "f"(hi));
    return r;
}
__device__ __forceinline__ float2 upk2(uint64_t v) {
    float2 f;
    asm("mov.b64 {%0, %1}, %2;" : "=f"(f.x), "=f"(f.y) : "l"(v));
    return f;
}

// ================= tensor-core GEMM: C[M,Nn] = A[M,K] @ B[Nn,K]^T =================
#define GEMM_STAGE 32768
#define GEMM_SMEM  (3 * GEMM_STAGE)

__device__ __forceinline__ uint32_t sw_off(int row, int c16) {
    return (uint32_t)(row * 64 + ((c16 ^ ((row >> 1) & 3)) << 4));
}

template <bool RELU>
__global__ __launch_bounds__(256, 2) void mma_gemm_k(
    const __nv_bfloat16* __restrict__ Ahi, const __nv_bfloat16* __restrict__ Alo,
    const __nv_bfloat16* __restrict__ Bhi, const __nv_bfloat16* __restrict__ Blo,
    const float* __restrict__ bias,
    float* __restrict__ C, __nv_bfloat16* __restrict__ Chi, __nv_bfloat16* __restrict__ Clo,
    int M, int Nn, int K)
{
    extern __shared__ char smem[];
    const uint32_t sbase = (uint32_t)__cvta_generic_to_shared(smem);
    const int tid = threadIdx.x, lane = tid & 31, wid = tid >> 5;
    const int wm = wid & 3, wn = wid >> 2;
    const int brow = blockIdx.y, bcol = blockIdx.x;
    const int NC = K >> 5;

    const __nv_bfloat16* srcs[4] = {
        Ahi + (size_t)(brow * 128) * K, Alo + (size_t)(brow * 128) * K,
        Bhi + (size_t)(bcol * 128) * K, Blo + (size_t)(bcol * 128) * K };

    auto issue = [&](int kc, int buf) {
        uint32_t bb = sbase + buf * GEMM_STAGE;
        int row = tid >> 2, c16 = tid & 3;
        uint32_t d = bb + sw_off(row, c16);
#pragma unroll
        for (int arr = 0; arr < 4; arr++) {
            const void* g0 = srcs[arr] + (size_t)row * K + kc * 32 + c16 * 8;
            const void* g1 = srcs[arr] + (size_t)(row + 64) * K + kc * 32 + c16 * 8;
            asm volatile("cp.async.cg.shared.global [%0], [%1], 16;"
                         :: "r"(d + arr * 8192), "l"(g0));
            asm volatile("cp.async.cg.shared.global [%0], [%1], 16;"
                         :: "r"(d + arr * 8192 + sw_off(64, 0)), "l"(g1));
        }
        asm volatile("cp.async.commit_group;" ::: "memory");
    };

    float acc[2][8][4];
#pragma unroll
    for (int i = 0; i < 2; i++)
#pragma unroll
        for (int j = 0; j < 8; j++)
#pragma unroll
            for (int k = 0; k < 4; k++) acc[i][j][k] = 0.f;

    issue(0, 0);
    if (NC > 1) issue(1, 1);
    if (NC > 2) issue(2, 2);

    const int a_row_off = ((lane >> 3) & 1) * 8 + (lane & 7);
    const int a_c16_off = lane >> 4;
    const int b_row_off = (lane >> 4) * 8 + (lane & 7);
    const int b_c16_off = (lane >> 3) & 1;

    for (int kc = 0; kc < NC; kc++) {
        int pend = NC - 1 - kc;
        if (pend >= 2)      asm volatile("cp.async.wait_group 2;" ::: "memory");
        else if (pend == 1) asm volatile("cp.async.wait_group 1;" ::: "memory");
        else                asm volatile("cp.async.wait_group 0;" ::: "memory");
        __syncthreads();

        const uint32_t bb = sbase + (kc % 3) * GEMM_STAGE;
        const uint32_t aHiB = bb, aLoB = bb + 8192, bHiB = bb + 16384, bLoB = bb + 24576;

#pragma unroll
        for (int ks = 0; ks < 2; ks++) {
            uint32_t ahi[2][4], alo[2][4];
#pragma unroll
            for (int mt = 0; mt < 2; mt++) {
                int row = wm * 32 + mt * 16 + a_row_off;
                uint32_t off = sw_off(row, ks * 2 + a_c16_off);
                ldmatrix_x4(ahi[mt], aHiB + off);
                ldmatrix_x4(alo[mt], aLoB + off);
            }
#pragma unroll
            for (int ng = 0; ng < 4; ng++) {
                int row = wn * 64 + ng * 16 + b_row_off;
                uint32_t off = sw_off(row, ks * 2 + b_c16_off);
                uint32_t bhi[4], blo[4];
                ldmatrix_x4(bhi, bHiB + off);
                ldmatrix_x4(blo, bLoB + off);
#pragma unroll
                for (int mt = 0; mt < 2; mt++)
#pragma unroll
                    for (int nt = 0; nt < 2; nt++) {
                        float* c = acc[mt][ng * 2 + nt];
                        mma_bf16(c, ahi[mt], bhi + nt * 2);
                        mma_bf16(c, ahi[mt], blo + nt * 2);
                        mma_bf16(c, alo[mt], bhi + nt * 2);
                    }
            }
        }
        __syncthreads();
        if (kc + 3 < NC) issue(kc + 3, (kc + 3) % 3);
    }

    const int rbase = brow * 128 + wm * 32 + (lane >> 2);
    const int cb0 = bcol * 128 + wn * 64 + (lane & 3) * 2;
#pragma unroll
    for (int mt = 0; mt < 2; mt++)
#pragma unroll
        for (int ni = 0; ni < 8; ni++) {
            float* c = acc[mt][ni];
            int col = cb0 + ni * 8;
            float b0 = bias ? bias[col] : 0.f;
            float b1 = bias ? bias[col + 1] : 0.f;
#pragma unroll
            for (int half = 0; half < 2; half++) {
                int row = rbase + mt * 16 + half * 8;
                float v0 = c[half * 2 + 0] + b0;
                float v1 = c[half * 2 + 1] + b1;
                if (RELU) { v0 = fmaxf(v0, 0.f); v1 = fmaxf(v1, 0.f); }
                size_t o = (size_t)row * Nn + col;
                if (C) *(float2*)(C + o) = make_float2(v0, v1);
                if (Chi) {
                    __nv_bfloat16 h0, l0, h1, l1;
                    split2(v0, h0, l0);
                    split2(v1, h1, l1);
                    *(__nv_bfloat162*)(Chi + o) = __nv_bfloat162(h0, h1);
                    *(__nv_bfloat162*)(Clo + o) = __nv_bfloat162(l0, l1);
                }
            }
        }
}

// ================= conversion kernels =================
__global__ void split_k(const float* __restrict__ x, __nv_bfloat16* __restrict__ hi,
                        __nv_bfloat16* __restrict__ lo, int n)
{
    int i = blockIdx.x * blockDim.x + threadIdx.x;
    if (i >= n) return;
    split2(x[i], hi[i], lo[i]);
}

__global__ void wsplit_t_k(const float* __restrict__ W, __nv_bfloat16* __restrict__ hi,
                           __nv_bfloat16* __restrict__ lo, int K, int Nc, int total)
{
    int i = blockIdx.x * blockDim.x + threadIdx.x;
    if (i >= total) return;
    int KN = K * Nc;
    int l = i / KN, r = i - l * KN;
    int n = r / K, k = r - n * K;
    split2(W[(size_t)l * KN + (size_t)k * Nc + n], hi[i], lo[i]);
}

// ================= CSR build =================
__global__ void csr_zero_k(int* __restrict__ cnt)
{
    int i = blockIdx.x * blockDim.x + threadIdx.x;
    if (i < N_) cnt[i] = 0;
}

__global__ void csr_count_k(const int* __restrict__ ei, int* __restrict__ cnt)
{
    int e = blockIdx.x * blockDim.x + threadIdx.x;
    if (e < E_) atomicAdd(&cnt[ei[E_ + e]], 1);
}

__global__ __launch_bounds__(1024) void csr_scan_k(int* __restrict__ cnt,
                                                   int* __restrict__ rowptr)
{
    __shared__ int ssum[1024];
    int t = threadIdx.x;
    int base = t * 16;
    int loc[16];
    int s = 0;
#pragma unroll
    for (int i = 0; i < 16; i++) { loc[i] = s; s += cnt[base + i]; }
    int own = s;
    ssum[t] = s;
    __syncthreads();
    for (int off = 1; off < 1024; off <<= 1) {
        int v = (t >= off) ? ssum[t - off] : 0;
        __syncthreads();
        ssum[t] += v;
        __syncthreads();
    }
    int excl = ssum[t] - own;
#pragma unroll
    for (int i = 0; i < 16; i++) {
        rowptr[base + i] = excl + loc[i];
        cnt[base + i] = excl + loc[i];
    }
    if (t == 1023) rowptr[N_] = excl + own;
}

__global__ void csr_scatter_k(const int* __restrict__ ei, int* __restrict__ cur,
                              int* __restrict__ csrc)
{
    int e = blockIdx.x * blockDim.x + threadIdx.x;
    if (e >= E_) return;
    int pos = atomicAdd(&cur[ei[E_ + e]], 1);
    csrc[pos] = ei[e];
}

// ================= GAT node scores =================
__global__ void node_scores_k(const float* __restrict__ xw,
                              const float* __restrict__ asrc,
                              const float* __restrict__ adst,
                              float* __restrict__ ssrc, float* __restrict__ sdst)
{
    int n = blockIdx.x, t = threadIdx.x;
    float xv = xw[(size_t)n * H_ + t];
    float a1 = xv * asrc[t];
    float a2 = xv * adst[t];
#pragma unroll
    for (int o = 16; o; o >>= 1) {
        a1 += __shfl_xor_sync(0xffffffffu, a1, o);
        a2 += __shfl_xor_sync(0xffffffffu, a2, o);
    }
    if ((t & 31) == 0) {
        ssrc[n * HEADS_ + (t >> 5)] = a1;
        sdst[n * HEADS_ + (t >> 5)] = a2;
    }
}

// ================= fused GAT aggregate + LN1 =================
#define GCH 128
__global__ __launch_bounds__(256) void gat_agg_ln_k(
    const int* __restrict__ csrc, const int* __restrict__ rowptr,
    const float* __restrict__ ssrc, const float* __restrict__ sdst,
    const float* __restrict__ xw, const float* __restrict__ x,
    const float* __restrict__ bg, const float* __restrict__ gamma,
    const float* __restrict__ beta, float* __restrict__ out)
{
    __shared__ int   srcsm[GCH];
    __shared__ float esc[GCH * HEADS_];
    int d = blockIdx.x, t = threadIdx.x, hd = t >> 5;
    int beg = rowptr[d], end = rowptr[d + 1];

    float acc = 0.f, asum = 0.f;
    for (int cs = beg; cs < end; cs += GCH) {
        int cn = min(GCH, end - cs);
        if (t < cn) srcsm[t] = csrc[cs + t];
        __syncthreads();
        for (int idx = t; idx < cn * HEADS_; idx += 256) {
            int j = idx >> 3, hh = idx & 7;
            float a = ssrc[srcsm[j] * HEADS_ + hh] + sdst[d * HEADS_ + hh];
            a = (a > 0.f) ? a : 0.2f * a;
            esc[idx] = __expf(a);
        }
        __syncthreads();
        for (int j = 0; j < cn; j++) {
            float e = esc[j * HEADS_ + hd];
            asum += e;
            acc += e * xw[(size_t)srcsm[j] * H_ + t];
        }
        __syncthreads();
    }
    float v = (asum > 0.f) ? acc / asum : 0.f;
    v += bg[t] + x[(size_t)d * H_ + t];

    float s1 = v, s2 = v * v;
#pragma unroll
    for (int o = 16; o; o >>= 1) {
        s1 += __shfl_xor_sync(0xffffffffu, s1, o);
        s2 += __shfl_xor_sync(0xffffffffu, s2, o);
    }
    __shared__ float ws[8], ws2[8];
    if ((t & 31) == 0) { ws[t >> 5] = s1; ws2[t >> 5] = s2; }
    __syncthreads();
    s1 = 0.f; s2 = 0.f;
#pragma unroll
    for (int i = 0; i < 8; i++) { s1 += ws[i]; s2 += ws2[i]; }
    float mean = s1 * (1.f / H_);
    float var = s2 * (1.f / H_) - mean * mean;
    out[(size_t)d * H_ + t] = (v - mean) * rsqrtf(var + 1e-5f) * gamma[t] + beta[t];
}

// ================= LayerNorm =================
__global__ void ln_k(const float* __restrict__ a, const float* __restrict__ b,
                     const float* __restrict__ gamma, const float* __restrict__ beta,
                     const float* __restrict__ addAfter, float* __restrict__ out,
                     __nv_bfloat16* __restrict__ ohi, __nv_bfloat16* __restrict__ olo)
{
    int n = blockIdx.x, t = threadIdx.x;
    size_t idx = (size_t)n * H_ + t;
    float v = a[idx];
    if (b) v += b[idx];
    float s = v, s2 = v * v;
#pragma unroll
    for (int o = 16; o; o >>= 1) {
        s += __shfl_xor_sync(0xffffffffu, s, o);
        s2 += __shfl_xor_sync(0xffffffffu, s2, o);
    }
    __shared__ float ws[8], ws2[8];
    if ((t & 31) == 0) { ws[t >> 5] = s; ws2[t >> 5] = s2; }
    __syncthreads();
    s = 0.f; s2 = 0.f;
#pragma unroll
    for (int i = 0; i < 8; i++) { s += ws[i]; s2 += ws2[i]; }
    float mean = s * (1.f / H_);
    float var = s2 * (1.f / H_) - mean * mean;
    float y = (v - mean) * rsqrtf(var + 1e-5f) * gamma[t] + beta[t];
    float res = (addAfter ? addAfter[idx] : 0.f) + y;
    if (out) out[idx] = res;
    if (ohi) {
        __nv_bfloat16 hi, lo;
        split2(res, hi, lo);
        ohi[idx] = hi;
        olo[idx] = lo;
    }
}

// ================= dense MHA (packed fp32x2 math) =================
__global__ __launch_bounds__(256) void mha_k(const float* __restrict__ qkv,
                                             __nv_bfloat16* __restrict__ atthi,
                                             __nv_bfloat16* __restrict__ attlo)
{
    extern __shared__ float sm[];          // ks[256*32] ++ vs[256*32] = 64 KB
    float* ks = sm;
    float* vs = sm + NB_ * OC_;
    int b = blockIdx.x / HEADS_;
    int h = blockIdx.x % HEADS_;
    int t = threadIdx.x;                   // query row

    // stage K,V (8-byte vectorized; offsets all even floats -> aligned)
    for (int idx = t; idx < NB_ * OC_ / 2; idx += 256) {
        int row = idx >> 4, c2 = idx & 15;
        const float* base = qkv + (size_t)(b * NB_ + row) * (3 * H_) + h * OC_ + c2 * 2;
        *(uint64_t*)(ks + idx * 2) = *(const uint64_t*)(base + H_);
        *(uint64_t*)(vs + idx * 2) = *(const uint64_t*)(base + 2 * H_);
    }
    __syncthreads();

    const float scale = 0.17677669529663687f;  // 1/sqrt(32)
    const float* qrow = qkv + (size_t)(b * NB_ + t) * (3 * H_) + h * OC_;
    uint64_t q2[16];
#pragma unroll
    for (int i = 0; i < 16; i++)
        q2[i] = pk2(qrow[2 * i] * scale, qrow[2 * i + 1] * scale);

    uint64_t o2[16];
#pragma unroll
    for (int i = 0; i < 16; i++) o2[i] = 0ull;
    float lsum = 0.f;

    const uint64_t* ks2 = (const uint64_t*)ks;
    const uint64_t* vs2 = (const uint64_t*)vs;

    for (int j = 0; j < NB_; j++) {
        uint64_t da = 0ull, db = 0ull;     // two dot chains for ILP
#pragma unroll
        for (int i = 0; i < 16; i += 2) {
            da = ffma2(q2[i],     ks2[j * 16 + i],     da);
            db = ffma2(q2[i + 1], ks2[j * 16 + i + 1], db);
        }
        float2 fa = upk2(da), fb = upk2(db);
        float s = (fa.x + fa.y) + (fb.x + fb.y);
        float p = __expf(s);
        lsum += p;
        uint64_t pp = pk2(p, p);
#pragma unroll
        for (int i = 0; i < 16; i++)
            o2[i] = ffma2(pp, vs2[j * 16 + i], o2[i]);
    }

    float inv = 1.f / lsum;
    size_t obase = (size_t)(b * NB_ + t) * H_ + h * OC_;
#pragma unroll
    for (int i = 0; i < 16; i++) {
        float2 ov = upk2(o2[i]);
        __nv_bfloat16 h0, l0, h1, l1;
        split2(ov.x * inv, h0, l0);
        split2(ov.y * inv, h1, l1);
        *(__nv_bfloat162*)(atthi + obase + 2 * i) = __nv_bfloat162(h0, h1);
        *(__nv_bfloat162*)(attlo + obase + 2 * i) = __nv_bfloat162(l0, l1);
    }
}

// ================= launcher =================
extern "C" void kernel_launch(void* const* d_in, const int* in_sizes, int n_in,
                              void* d_out, int out_size)
{
    const float* x_in = (const float*)d_in[0];
    const int*   ei   = (const int*)d_in[1];
    const float* wi   = (const float*)d_in[2];
    const float* bi   = (const float*)d_in[3];
    const float* wg   = (const float*)d_in[4];
    const float* asrc = (const float*)d_in[5];
    const float* adst = (const float*)d_in[6];
    const float* bg   = (const float*)d_in[7];
    const float* g1   = (const float*)d_in[8];
    const float* b1   = (const float*)d_in[9];
    const float* inw  = (const float*)d_in[10];
    const float* inb  = (const float*)d_in[11];
    const float* ow   = (const float*)d_in[12];
    const float* ob   = (const float*)d_in[13];
    const float* g2   = (const float*)d_in[14];
    const float* b2   = (const float*)d_in[15];
    const float* mw1  = (const float*)d_in[16];
    const float* mb1  = (const float*)d_in[17];
    const float* mw2  = (const float*)d_in[18];
    const float* mb2  = (const float*)d_in[19];
    const float* g3   = (const float*)d_in[20];
    const float* b3   = (const float*)d_in[21];
    const float* gf   = (const float*)d_in[22];
    const float* bf   = (const float*)d_in[23];
    const float* wo   = (const float*)d_in[24];
    const float* bo   = (const float*)d_in[25];
    float* out = (float*)d_out;

    float *px, *pxw, *ph, *pout, *pqkv, *po, *pss, *psd;
    int *pcnt, *prp, *pcsrc;
    __nv_bfloat16 *pxhi, *pxlo, *pahi, *palo, *pohi, *polo, *phhi, *phlo, *pwhi, *pwlo;
    cudaGetSymbolAddress((void**)&px,   g_x);
    cudaGetSymbolAddress((void**)&pxw,  g_xw);
    cudaGetSymbolAddress((void**)&ph,   g_h);
    cudaGetSymbolAddress((void**)&pout, g_out);
    cudaGetSymbolAddress((void**)&pqkv, g_qkv);
    cudaGetSymbolAddress((void**)&po,   g_o);
    cudaGetSymbolAddress((void**)&pss,  g_ssrc);
    cudaGetSymbolAddress((void**)&psd,  g_sdst);
    cudaGetSymbolAddress((void**)&pcnt, g_cnt);
    cudaGetSymbolAddress((void**)&prp,  g_rowptr);
    cudaGetSymbolAddress((void**)&pcsrc, g_csrc);
    cudaGetSymbolAddress((void**)&pxhi, g_xhi);
    cudaGetSymbolAddress((void**)&pxlo, g_xlo);
    cudaGetSymbolAddress((void**)&pahi, g_ahi);
    cudaGetSymbolAddress((void**)&palo, g_alo);
    cudaGetSymbolAddress((void**)&pohi, g_ohi);
    cudaGetSymbolAddress((void**)&polo, g_olo);
    cudaGetSymbolAddress((void**)&phhi, g_hhi);
    cudaGetSymbolAddress((void**)&phlo, g_hlo);
    cudaGetSymbolAddress((void**)&pwhi, g_whi);
    cudaGetSymbolAddress((void**)&pwlo, g_wlo);

    cudaFuncSetAttribute((const void*)mha_k,
                         cudaFuncAttributeMaxDynamicSharedMemorySize, 64 * 1024);
    cudaFuncSetAttribute((const void*)mma_gemm_k<false>,
                         cudaFuncAttributeMaxDynamicSharedMemorySize, GEMM_SMEM);
    cudaFuncSetAttribute((const void*)mma_gemm_k<true>,
                         cudaFuncAttributeMaxDynamicSharedMemorySize, GEMM_SMEM);

    // ---- prologue ordered so early launches (#4/#6) are real GEMMs for ncu ----
    wsplit_t_k<<<(32768 + 255) / 256, 256>>>(wi, pwhi + WI_OFF, pwlo + WI_OFF, IN_, H_, 32768);          // 1
    wsplit_t_k<<<(4 * 65536 + 255) / 256, 256>>>(wg, pwhi + WG_OFF, pwlo + WG_OFF, H_, H_, 4 * 65536);   // 2
    split_k<<<(N_ * IN_ + 255) / 256, 256>>>(x_in, phhi, phlo, N_ * IN_);                                 // 3
    mma_gemm_k<true><<<dim3(H_ / 128, N_ / 128), 256, GEMM_SMEM>>>(                                       // 4
        phhi, phlo, pwhi + WI_OFF, pwlo + WI_OFF, bi, px, pxhi, pxlo, N_, H_, IN_);
    csr_zero_k<<<N_ / 256, 256>>>(pcnt);                                                                  // 5
    mma_gemm_k<false><<<dim3(H_ / 128, N_ / 128), 256, GEMM_SMEM>>>(                                      // 6 <- ncu target
        pxhi, pxlo, pwhi + WG_OFF, pwlo + WG_OFF, nullptr, pxw, nullptr, nullptr, N_, H_, H_);
    csr_count_k<<<E_ / 256, 256>>>(ei, pcnt);
    csr_scan_k<<<1, 1024>>>(pcnt, prp);
    split_k<<<(4 * 196608 + 255) / 256, 256>>>(inw, pwhi + INW_OFF, pwlo + INW_OFF, 4 * 196608);
    split_k<<<(4 * 65536 + 255) / 256, 256>>>(ow, pwhi + OW_OFF, pwlo + OW_OFF, 4 * 65536);
    wsplit_t_k<<<(4 * 131072 + 255) / 256, 256>>>(mw1, pwhi + MW1_OFF, pwlo + MW1_OFF, H_, 2 * H_, 4 * 131072);
    wsplit_t_k<<<(4 * 131072 + 255) / 256, 256>>>(mw2, pwhi + MW2_OFF, pwlo + MW2_OFF, 2 * H_, H_, 4 * 131072);
    wsplit_t_k<<<(65536 + 255) / 256, 256>>>(wo, pwhi + WO_OFF, pwlo + WO_OFF, H_, OUT_, 65536);
    csr_scatter_k<<<E_ / 256, 256>>>(ei, pcnt, pcsrc);

    for (int l = 0; l < L_; l++) {
        const float* bg_l  = bg  + (size_t)l * H_;
        const float* g1_l  = g1  + (size_t)l * H_;
        const float* b1_l  = b1  + (size_t)l * H_;
        const float* inb_l = inb + (size_t)l * 3 * H_;
        const float* ob_l  = ob  + (size_t)l * H_;
        const float* g2_l  = g2  + (size_t)l * H_;
        const float* b2_l  = b2  + (size_t)l * H_;
        const float* mb1_l = mb1 + (size_t)l * 2 * H_;
        const float* mb2_l = mb2 + (size_t)l * H_;
        const float* g3_l  = g3  + (size_t)l * H_;
        const float* b3_l  = b3  + (size_t)l * H_;

        // ---- GAT local branch (layer 0's wg GEMM already done in prologue) ----
        if (l > 0)
            mma_gemm_k<false><<<dim3(H_ / 128, N_ / 128), 256, GEMM_SMEM>>>(
                pxhi, pxlo, pwhi + WG_OFF + l * 65536, pwlo + WG_OFF + l * 65536,
                nullptr, pxw, nullptr, nullptr, N_, H_, H_);
        node_scores_k<<<N_, 256>>>(pxw, asrc + (size_t)l * H_, adst + (size_t)l * H_, pss, psd);
        gat_agg_ln_k<<<N_, 256>>>(pcsrc, prp, pss, psd, pxw, px, bg_l, g1_l, b1_l, ph);

        // ---- global MHA branch ----
        mma_gemm_k<false><<<dim3(3 * H_ / 128, N_ / 128), 256, GEMM_SMEM>>>(
            pxhi, pxlo, pwhi + INW_OFF + l * 196608, pwlo + INW_OFF + l * 196608,
            inb_l, pqkv, nullptr, nullptr, N_, 3 * H_, H_);
        mha_k<<<B_ * HEADS_, 256, 64 * 1024>>>(pqkv, pahi, palo);
        mma_gemm_k<false><<<dim3(H_ / 128, N_ / 128), 256, GEMM_SMEM>>>(
            pahi, palo, pwhi + OW_OFF + l * 65536, pwlo + OW_OFF + l * 65536,
            ob_l, po, nullptr, nullptr, N_, H_, H_);
        ln_k<<<N_, 256>>>(po, px, g2_l, b2_l, ph, pout, pohi, polo);

        // ---- MLP + norm3 ----
        mma_gemm_k<true><<<dim3(2 * H_ / 128, N_ / 128), 256, GEMM_SMEM>>>(
            pohi, polo, pwhi + MW1_OFF + l * 131072, pwlo + MW1_OFF + l * 131072,
            mb1_l, nullptr, phhi, phlo, N_, 2 * H_, H_);
        mma_gemm_k<false><<<dim3(H_ / 128, N_ / 128), 256, GEMM_SMEM>>>(
            phhi, phlo, pwhi + MW2_OFF + l * 131072, pwlo + MW2_OFF + l * 131072,
            mb2_l, ph, nullptr, nullptr, N_, H_, 2 * H_);
        ln_k<<<N_, 256>>>(pout, ph, g3_l, b3_l, nullptr, px, pxhi, pxlo);
    }

    // final LN + output projection
    ln_k<<<N_, 256>>>(px, nullptr, gf, bf, nullptr, nullptr, pahi, palo);
    mma_gemm_k<false><<<dim3(OUT_ / 128, N_ / 128), 256, GEMM_SMEM>>>(
        pahi, palo, pwhi + WO_OFF, pwlo + WO_OFF, bo, out, nullptr, nullptr, N_, OUT_, H_);
}